// round 14
// baseline (speedup 1.0000x reference)
#include <cuda_runtime.h>
#include <cuda_fp16.h>
#include <math.h>
#include <stdint.h>

#define HDIM 1024
#define NDIM 2048
#define NEXP 8
#define MTOK 16384
#define BM 128
#define BN 128
#define BK 32
#define KT (HDIM / BK)
#define GAP_TH 5e-4f
#define MAXFLAG 8192

#define ST_AH 0
#define ST_BH 10240
#define ST_BL 20480
#define STG   30720
#define OFF_W2 (2 * STG)
#define OFF_B1 (OFF_W2 + BN * NEXP * 4)
#define SMEM_DYN (OFF_B1 + BN * 4)

// repairA dynamic smem (floats): xs[2][16][68], ws[2][64][68]
#define RPN  64
#define XSZ  (16 * 68)
#define WSZ  (RPN * 68)
#define WOFF (2 * XSZ)
#define RP_DYN ((2 * XSZ + 2 * WSZ) * 4)   // 43520 B

__device__ __half g_wh[NDIM * HDIM];
__device__ __half g_wl[NDIM * HDIM];
__device__ float  g_w1tf[NDIM * HDIM];
__device__ float  g_ewfix[MAXFLAG * NEXP];
__device__ float  g_usage[NEXP];
__device__ int    g_count, g_nflag;
__device__ int    g_list[MAXFLAG];

__device__ __forceinline__ uint32_t smem_u32(const void* p) {
    uint32_t a;
    asm("{ .reg .u64 t; cvta.to.shared.u64 t, %1; cvt.u32.u64 %0, t; }" : "=r"(a) : "l"(p));
    return a;
}
__device__ __forceinline__ void cp16(uint32_t s, const void* g) {
    asm volatile("cp.async.cg.shared.global [%0], [%1], 16;" :: "r"(s), "l"(g));
}
__device__ __forceinline__ void cp_commit() { asm volatile("cp.async.commit_group;" ::: "memory"); }
__device__ __forceinline__ void cp_wait0()  { asm volatile("cp.async.wait_group 0;" ::: "memory"); }
__device__ __forceinline__ void ldm4(uint32_t* r, uint32_t a) {
    asm volatile("ldmatrix.sync.aligned.m8n8.x4.shared.b16 {%0,%1,%2,%3}, [%4];"
                 : "=r"(r[0]), "=r"(r[1]), "=r"(r[2]), "=r"(r[3]) : "r"(a));
}
__device__ __forceinline__ void mma(float* c, const uint32_t* a, const uint32_t* b) {
    asm volatile("mma.sync.aligned.m16n8k16.row.col.f32.f16.f16.f32 "
                 "{%0,%1,%2,%3}, {%4,%5,%6,%7}, {%8,%9}, {%0,%1,%2,%3};"
                 : "+f"(c[0]), "+f"(c[1]), "+f"(c[2]), "+f"(c[3])
                 : "r"(a[0]), "r"(a[1]), "r"(a[2]), "r"(a[3]), "r"(b[0]), "r"(b[1]));
}

// ---------- kernel 0: w1^T split (fp16 hi/lo + fp32 copy) + init ----------
__global__ void pre_kernel(const float* __restrict__ w1, float* __restrict__ ew,
                           const float* __restrict__ b2) {
    __shared__ float tile[32][33];
    const int b = blockIdx.x, t = threadIdx.x;
    if (b < 2048) {
        const int nb = (b & 63) * 32, kb = (b >> 6) * 32;
        const int tx = t & 31, ty = t >> 5;
#pragma unroll
        for (int i = 0; i < 4; ++i)
            tile[ty + i * 8][tx] = w1[(size_t)(kb + ty + i * 8) * NDIM + nb + tx];
        __syncthreads();
#pragma unroll
        for (int i = 0; i < 4; ++i) {
            int row = ty + i * 8;
            float orig = tile[tx][row];
            float v = orig * 1024.0f;
            __half h = __float2half_rn(v);
            __half l = __float2half_rn(v - __half2float(h));
            size_t o = (size_t)(nb + row) * HDIM + kb + tx;
            g_wh[o] = h; g_wl[o] = l; g_w1tf[o] = orig;
        }
    } else {
        const int i = (b - 2048) * 256 + t;
        if (i < MTOK * NEXP) ew[i] = b2[i & 7];
        if (b == 2048) {
            if (t < NEXP) g_usage[t] = 0.f;
            if (t == 0) { g_count = 0; g_nflag = 0; }
        }
    }
}

// ---------- kernel 1: GEMM (ah*(bh+bl)) + GELU + GEMM2 (R9 2-stage, unchanged) ----
__global__ __launch_bounds__(256, 2)
void gemm_kernel(const float* __restrict__ x, const float* __restrict__ b1,
                 const float* __restrict__ w2, float* __restrict__ ew) {
    extern __shared__ char smem[];
    const uint32_t sb = smem_u32(smem);
    const int t = threadIdx.x, w = t >> 5, lane = t & 31;
    const int wm = w & 3, wn = w >> 2;
    const int n0 = blockIdx.x * BN, m0 = blockIdx.y * BM;

    float* w2s = (float*)(smem + OFF_W2);
    float* b1s = (float*)(smem + OFF_B1);
    for (int i = t; i < BN * NEXP; i += 256) w2s[i] = w2[(size_t)n0 * NEXP + i];
    for (int i = t; i < BN; i += 256)        b1s[i] = b1[n0 + i];

    const int rA = t >> 1;
    const float* xg = x + (size_t)(m0 + rA) * HDIM + (t & 1) * 16;
    const size_t gb0 = (size_t)(n0 + rA) * HDIM;

#define LOAD_B(stg, kt_)                                                     \
    {                                                                        \
        uint32_t _bs = sb + (stg) * STG + rA * 80;                           \
        size_t _kb = gb0 + (size_t)(kt_) * BK;                               \
        _Pragma("unroll")                                                    \
        for (int j = 0; j < 2; ++j) {                                        \
            int c16 = (t & 1) * 2 + j;                                       \
            cp16(_bs + ST_BH + c16 * 16, g_wh + _kb + c16 * 8);              \
            cp16(_bs + ST_BL + c16 * 16, g_wl + _kb + c16 * 8);              \
        }                                                                    \
    }

#define STS_A(stg, ra_)                                                      \
    {                                                                        \
        uint32_t hws[8];                                                     \
        _Pragma("unroll")                                                    \
        for (int wi = 0; wi < 4; ++wi) {                                     \
            const float* fp = (const float*)&(ra_)[wi];                      \
            __half2 p01 = __halves2half2(__float2half_rn(fp[0]),             \
                                         __float2half_rn(fp[1]));            \
            __half2 p23 = __halves2half2(__float2half_rn(fp[2]),             \
                                         __float2half_rn(fp[3]));            \
            hws[wi*2] = *(uint32_t*)&p01; hws[wi*2+1] = *(uint32_t*)&p23;    \
        }                                                                    \
        char* _p = smem + (stg) * STG + ST_AH + rA * 80 + (t & 1) * 32;      \
        *(uint4*)(_p)      = make_uint4(hws[0], hws[1], hws[2], hws[3]);     \
        *(uint4*)(_p + 16) = make_uint4(hws[4], hws[5], hws[6], hws[7]);     \
    }

    float4 ra[4];
#pragma unroll
    for (int i = 0; i < 4; ++i) ra[i] = *(const float4*)(xg + 4 * i);
    LOAD_B(0, 0); cp_commit();
    STS_A(0, ra);
#pragma unroll
    for (int i = 0; i < 4; ++i) ra[i] = *(const float4*)(xg + BK + 4 * i);

    float acc[2][8][4];
#pragma unroll
    for (int mi = 0; mi < 2; ++mi)
#pragma unroll
        for (int ni = 0; ni < 8; ++ni)
#pragma unroll
            for (int c = 0; c < 4; ++c) acc[mi][ni][c] = 0.f;

    const uint32_t aoff = ((lane & 7) + ((lane >> 3) & 1) * 8) * 80 + ((lane >> 4) & 1) * 16;
    const uint32_t* s32m = (const uint32_t*)smem;
    const int bword0 = (ST_BH + (wn * 64 + (lane >> 2)) * 80 + (lane & 3) * 4) >> 2;
    const int BLOFF = (ST_BL - ST_BH) >> 2;

    for (int kt = 0; kt < KT; ++kt) {
        cp_wait0();
        __syncthreads();
        if (kt + 1 < KT) { LOAD_B((kt + 1) & 1, kt + 1); cp_commit(); STS_A((kt + 1) & 1, ra); }
        if (kt + 2 < KT) {
#pragma unroll
            for (int i = 0; i < 4; ++i) ra[i] = *(const float4*)(xg + (kt + 2) * BK + 4 * i);
        }
        const uint32_t bs = sb + (kt & 1) * STG;
        const int sw = ((kt & 1) * STG) >> 2;
#pragma unroll
        for (int kk = 0; kk < 2; ++kk) {
            uint32_t ah[2][4];
#pragma unroll
            for (int mi = 0; mi < 2; ++mi)
                ldm4(ah[mi], bs + ST_AH + (wm * 32 + mi * 16) * 80 + kk * 32 + aoff);
#pragma unroll
            for (int ni = 0; ni < 8; ++ni) {
                int bo = sw + bword0 + (ni * 8 * 80 + kk * 32) / 4;
                uint32_t bh[2] = { s32m[bo], s32m[bo + 4] };
                uint32_t bl[2] = { s32m[bo + BLOFF], s32m[bo + BLOFF + 4] };
#pragma unroll
                for (int mi = 0; mi < 2; ++mi) {
                    mma(acc[mi][ni], ah[mi], bh);
                    mma(acc[mi][ni], ah[mi], bl);
                }
            }
        }
    }

    float part[4][NEXP];
#pragma unroll
    for (int p = 0; p < 4; ++p)
#pragma unroll
        for (int e = 0; e < NEXP; ++e) part[p][e] = 0.f;
    const float isc = 1.0f / 1024.0f;
#pragma unroll
    for (int mi = 0; mi < 2; ++mi)
#pragma unroll
        for (int h = 0; h < 2; ++h) {
            const int pi = mi * 2 + h;
#pragma unroll
            for (int ni = 0; ni < 8; ++ni) {
                int nl = wn * 64 + ni * 8 + (lane & 3) * 2;
                float v0 = acc[mi][ni][h * 2] * isc + b1s[nl];
                float v1 = acc[mi][ni][h * 2 + 1] * isc + b1s[nl + 1];
                float g0 = 0.5f * v0 * (1.0f + erff(v0 * 0.7071067811865475f));
                float g1 = 0.5f * v1 * (1.0f + erff(v1 * 0.7071067811865475f));
                const float* wr = w2s + nl * NEXP;
#pragma unroll
                for (int e = 0; e < NEXP; ++e)
                    part[pi][e] = fmaf(g0, wr[e], fmaf(g1, wr[NEXP + e], part[pi][e]));
            }
        }
#pragma unroll
    for (int p = 0; p < 4; ++p)
#pragma unroll
        for (int e = 0; e < NEXP; ++e) {
            float v = part[p][e];
            v += __shfl_xor_sync(0xffffffffu, v, 1);
            v += __shfl_xor_sync(0xffffffffu, v, 2);
            part[p][e] = v;
        }
    if ((lane & 3) == 0)
#pragma unroll
        for (int p = 0; p < 4; ++p) {
            int r = m0 + wm * 32 + (p >> 1) * 16 + (p & 1) * 8 + (lane >> 2);
#pragma unroll
            for (int e = 0; e < NEXP; ++e)
                atomicAdd(&ew[(size_t)r * NEXP + e], part[p][e]);
        }
}

// ---------- kernel 2: top-2 + masks + usage; flag near top2/top3 ties ----------
__global__ void topk_kernel(const float* __restrict__ ew, float* __restrict__ masks,
                            const float* __restrict__ b2, int M) {
    __shared__ float su[NEXP];
    __shared__ int sc;
    const int t = threadIdx.x;
    if (t < NEXP) su[t] = 0.f;
    if (t == 0)   sc = 0;
    __syncthreads();
    const int tok = blockIdx.x * blockDim.x + t;
    if (tok < M) {
        float v[NEXP];
        float4 a = *(const float4*)(ew + (size_t)tok * NEXP);
        float4 b = *(const float4*)(ew + (size_t)tok * NEXP + 4);
        v[0]=a.x; v[1]=a.y; v[2]=a.z; v[3]=a.w; v[4]=b.x; v[5]=b.y; v[6]=b.z; v[7]=b.w;
        int i1 = 0; float m1 = v[0];
#pragma unroll
        for (int e = 1; e < NEXP; ++e) if (v[e] > m1) { m1 = v[e]; i1 = e; }
        int i2 = -1; float m2 = -3.4e38f;
#pragma unroll
        for (int e = 0; e < NEXP; ++e) if (e != i1 && v[e] > m2) { m2 = v[e]; i2 = e; }
        float m3 = -3.4e38f;
#pragma unroll
        for (int e = 0; e < NEXP; ++e) if (e != i1 && e != i2 && v[e] > m3) m3 = v[e];
        bool flagged = false;
        if (m2 - m3 < GAP_TH) {
            int idx = atomicAdd(&g_nflag, 1);
            if (idx < MAXFLAG) {
                flagged = true;
                g_list[idx] = tok;
#pragma unroll
                for (int e = 0; e < NEXP; ++e) g_ewfix[idx * NEXP + e] = b2[e];
            }
        }
        if (!flagged) {
            float ex = expf(m2 - m1);
            float p1 = 1.f / (1.f + ex), p2 = ex / (1.f + ex);
            float o[NEXP];
#pragma unroll
            for (int e = 0; e < NEXP; ++e) o[e] = (e == i1) ? p1 : ((e == i2) ? p2 : 0.f);
            *(float4*)(masks + (size_t)tok * NEXP)     = make_float4(o[0], o[1], o[2], o[3]);
            *(float4*)(masks + (size_t)tok * NEXP + 4) = make_float4(o[4], o[5], o[6], o[7]);
            atomicAdd(&su[i1], p1);
            atomicAdd(&su[i2], p2);
            atomicAdd(&sc, (p1 > 0.f) + (p2 > 0.f));
        }
    }
    __syncthreads();
    if (t < NEXP) atomicAdd(&g_usage[t], su[t]);
    if (t == 0)   atomicAdd(&g_count, sc);
}

// ---------- kernel 3a: batched exact recompute, 64-n blocks, double-buffered ----
// grid (32 n-blocks, 16 token stripes); block tile 16 tok x 64 n, thread 2x2
__global__ __launch_bounds__(256)
void repairA_kernel(const float* __restrict__ x, const float* __restrict__ b1,
                    const float* __restrict__ w2) {
    extern __shared__ float dsm[];     // xs[2][16][68] @0, ws[2][64][68] @WOFF
    __shared__ float w2s[RPN * NEXP];
    __shared__ float sew[16][NEXP];
    const int t = threadIdx.x;
    const int nb = blockIdx.x * RPN;
    const int nf = min(g_nflag, MAXFLAG);
    if ((int)blockIdx.y * 16 >= nf) return;
    const int tg = t & 7, ng = t >> 3;       // 2 toks, 2 n per thread

    for (int i = t; i < RPN * NEXP; i += 256) w2s[i] = w2[(size_t)nb * NEXP + i];

    const int xrow = t >> 4, xcol = (t & 15) * 4;
    const float* wbase = g_w1tf + (size_t)nb * HDIM;

    for (int tokbase = blockIdx.y * 16; tokbase < nf; tokbase += 16 * gridDim.y) {
        if (t < 128) sew[t >> 3][t & 7] = 0.f;
        float acc[2][2] = {{0.f, 0.f}, {0.f, 0.f}};

        const int ti = tokbase + xrow;
        const float* xrp = (ti < nf) ? (x + (size_t)g_list[ti] * HDIM) : 0;

        float4 xr = xrp ? *(const float4*)(xrp + xcol) : make_float4(0.f, 0.f, 0.f, 0.f);
        float4 wr[4];
#pragma unroll
        for (int i = 0; i < 4; ++i) {
            int idx = i * 256 + t;
            wr[i] = *(const float4*)(wbase + (size_t)(idx >> 4) * HDIM + (idx & 15) * 4);
        }

        for (int kc = 0; kc < 16; ++kc) {
            const int buf = kc & 1;
            float* xsp = dsm + buf * XSZ;
            float* wsp = dsm + WOFF + buf * WSZ;
            *(float4*)&xsp[xrow * 68 + xcol] = xr;
#pragma unroll
            for (int i = 0; i < 4; ++i) {
                int idx = i * 256 + t;
                *(float4*)&wsp[(idx >> 4) * 68 + (idx & 15) * 4] = wr[i];
            }
            __syncthreads();
            if (kc + 1 < 16) {
                xr = xrp ? *(const float4*)(xrp + (kc + 1) * 64 + xcol)
                         : make_float4(0.f, 0.f, 0.f, 0.f);
#pragma unroll
                for (int i = 0; i < 4; ++i) {
                    int idx = i * 256 + t;
                    wr[i] = *(const float4*)(wbase + (size_t)(idx >> 4) * HDIM
                                             + (kc + 1) * 64 + (idx & 15) * 4);
                }
            }
#pragma unroll 4
            for (int kq = 0; kq < 16; ++kq) {
                float4 x0 = *(float4*)&xsp[(tg * 2) * 68 + kq * 4];
                float4 x1 = *(float4*)&xsp[(tg * 2 + 1) * 68 + kq * 4];
#pragma unroll
                for (int j = 0; j < 2; ++j) {
                    float4 wv = *(float4*)&wsp[(ng * 2 + j) * 68 + kq * 4];
                    acc[0][j] = fmaf(x0.x, wv.x, fmaf(x0.y, wv.y,
                                fmaf(x0.z, wv.z, fmaf(x0.w, wv.w, acc[0][j]))));
                    acc[1][j] = fmaf(x1.x, wv.x, fmaf(x1.y, wv.y,
                                fmaf(x1.z, wv.z, fmaf(x1.w, wv.w, acc[1][j]))));
                }
            }
        }
        __syncthreads();
#pragma unroll
        for (int i = 0; i < 2; ++i) {
            float part[NEXP];
#pragma unroll
            for (int e = 0; e < NEXP; ++e) part[e] = 0.f;
#pragma unroll
            for (int j = 0; j < 2; ++j) {
                int n = ng * 2 + j;
                float v = acc[i][j] + b1[nb + n];
                float g = 0.5f * v * (1.0f + erff(v * 0.7071067811865475f));
#pragma unroll
                for (int e = 0; e < NEXP; ++e)
                    part[e] = fmaf(g, w2s[n * NEXP + e], part[e]);
            }
#pragma unroll
            for (int e = 0; e < NEXP; ++e)
                atomicAdd(&sew[tg * 2 + i][e], part[e]);
        }
        __syncthreads();
        if (t < 128) {
            int tw = tokbase + (t >> 3);
            if (tw < nf)
                atomicAdd(&g_ewfix[tw * NEXP + (t & 7)], sew[t >> 3][t & 7]);
        }
        __syncthreads();
    }
}

// ---------- kernel 3b: flagged masks/usage + losses (single block) ----------
__global__ void repairB_kernel(float* __restrict__ masks, float* __restrict__ tail, int M) {
    __shared__ float su[NEXP];
    __shared__ int sc;
    const int t = threadIdx.x;
    if (t < NEXP) su[t] = 0.f;
    if (t == 0)   sc = 0;
    __syncthreads();
    const int nf = min(g_nflag, MAXFLAG);
    for (int it = t; it < nf; it += 256) {
        const int tok = g_list[it];
        float v[NEXP];
#pragma unroll
        for (int e = 0; e < NEXP; ++e) v[e] = g_ewfix[it * NEXP + e];
        int i1 = 0; float m1 = v[0];
#pragma unroll
        for (int e = 1; e < NEXP; ++e) if (v[e] > m1) { m1 = v[e]; i1 = e; }
        int i2 = -1; float m2 = -3.4e38f;
#pragma unroll
        for (int e = 0; e < NEXP; ++e) if (e != i1 && v[e] > m2) { m2 = v[e]; i2 = e; }
        float ex = expf(m2 - m1);
        float p1 = 1.f / (1.f + ex), p2 = ex / (1.f + ex);
        float o[NEXP];
#pragma unroll
        for (int e = 0; e < NEXP; ++e) o[e] = (e == i1) ? p1 : ((e == i2) ? p2 : 0.f);
        *(float4*)(masks + (size_t)tok * NEXP)     = make_float4(o[0], o[1], o[2], o[3]);
        *(float4*)(masks + (size_t)tok * NEXP + 4) = make_float4(o[4], o[5], o[6], o[7]);
        atomicAdd(&su[i1], p1);
        atomicAdd(&su[i2], p2);
        atomicAdd(&sc, (p1 > 0.f) + (p2 > 0.f));
    }
    __syncthreads();
    if (t == 0) {
        float u[NEXP], s = 0.f;
#pragma unroll
        for (int e = 0; e < NEXP; ++e) { u[e] = g_usage[e] + su[e]; s += u[e]; }
        float lb = 0.f;
#pragma unroll
        for (int e = 0; e < NEXP; ++e) {
            float un = u[e] / s;
            tail[1 + e] = un;
            float d = un - 0.125f;
            lb += d * d;
        }
        lb *= (1.f / 8.f);
        tail[0] = lb + 0.1f * (((float)(g_count + sc) / (float)M) * 0.5f);
    }
}

// ---------- launch ----------
extern "C" void kernel_launch(void* const* d_in, const int* in_sizes, int n_in,
                              void* d_out, int out_size) {
    const float* x  = (const float*)d_in[0];
    const float* w1 = (const float*)d_in[1];
    const float* b1 = (const float*)d_in[2];
    const float* w2 = (const float*)d_in[3];
    const float* b2 = (const float*)d_in[4];
    float* out   = (float*)d_out;
    const int M  = in_sizes[0] / HDIM;
    float* ew    = out;
    float* masks = out + (size_t)M * NEXP;
    float* tail  = out + (size_t)2 * M * NEXP;

    cudaFuncSetAttribute(gemm_kernel, cudaFuncAttributeMaxDynamicSharedMemorySize, SMEM_DYN);
    cudaFuncSetAttribute(repairA_kernel, cudaFuncAttributeMaxDynamicSharedMemorySize, RP_DYN);

    pre_kernel<<<2048 + (M * NEXP + 255) / 256, 256>>>(w1, ew, b2);
    gemm_kernel<<<dim3(NDIM / BN, M / BM), 256, SMEM_DYN>>>(x, b1, w2, ew);
    topk_kernel<<<(M + 255) / 256, 256>>>(ew, masks, b2, M);
    repairA_kernel<<<dim3(32, 16), 256, RP_DYN>>>(x, b1, w2);
    repairB_kernel<<<1, 256>>>(masks, tail, M);
}

// round 15
// speedup vs baseline: 1.0007x; 1.0007x over previous
#include <cuda_runtime.h>
#include <cuda_fp16.h>
#include <math.h>
#include <stdint.h>

#define HDIM 1024
#define NDIM 2048
#define NEXP 8
#define MTOK 16384
#define BM 128
#define BN 128
#define BK 32
#define KT (HDIM / BK)
#define GAP_TH 5e-4f
#define MAXFLAG 8192

#define ST_AH 0
#define ST_BH 10240
#define ST_BL 20480
#define STG   30720
#define OFF_W2 (2 * STG)
#define OFF_B1 (OFF_W2 + BN * NEXP * 4)
#define SMEM_DYN (OFF_B1 + BN * 4)

__device__ __half g_wh[NDIM * HDIM];
__device__ __half g_wl[NDIM * HDIM];
__device__ float  g_w1tf[NDIM * HDIM];
__device__ float  g_ewfix[MAXFLAG * NEXP];
__device__ float  g_usage[NEXP];
__device__ int    g_count, g_nflag;
__device__ int    g_list[MAXFLAG];

__device__ __forceinline__ uint32_t smem_u32(const void* p) {
    uint32_t a;
    asm("{ .reg .u64 t; cvta.to.shared.u64 t, %1; cvt.u32.u64 %0, t; }" : "=r"(a) : "l"(p));
    return a;
}
__device__ __forceinline__ void cp16(uint32_t s, const void* g) {
    asm volatile("cp.async.cg.shared.global [%0], [%1], 16;" :: "r"(s), "l"(g));
}
__device__ __forceinline__ void cp_commit() { asm volatile("cp.async.commit_group;" ::: "memory"); }
__device__ __forceinline__ void cp_wait0()  { asm volatile("cp.async.wait_group 0;" ::: "memory"); }
__device__ __forceinline__ void ldm4(uint32_t* r, uint32_t a) {
    asm volatile("ldmatrix.sync.aligned.m8n8.x4.shared.b16 {%0,%1,%2,%3}, [%4];"
                 : "=r"(r[0]), "=r"(r[1]), "=r"(r[2]), "=r"(r[3]) : "r"(a));
}
__device__ __forceinline__ void mma(float* c, const uint32_t* a, const uint32_t* b) {
    asm volatile("mma.sync.aligned.m16n8k16.row.col.f32.f16.f16.f32 "
                 "{%0,%1,%2,%3}, {%4,%5,%6,%7}, {%8,%9}, {%0,%1,%2,%3};"
                 : "+f"(c[0]), "+f"(c[1]), "+f"(c[2]), "+f"(c[3])
                 : "r"(a[0]), "r"(a[1]), "r"(a[2]), "r"(a[3]), "r"(b[0]), "r"(b[1]));
}

// ---------- kernel 0: w1^T split (fp16 hi/lo + fp32 copy) + init ----------
__global__ void pre_kernel(const float* __restrict__ w1, float* __restrict__ ew,
                           const float* __restrict__ b2) {
    __shared__ float tile[32][33];
    const int b = blockIdx.x, t = threadIdx.x;
    if (b < 2048) {
        const int nb = (b & 63) * 32, kb = (b >> 6) * 32;
        const int tx = t & 31, ty = t >> 5;
#pragma unroll
        for (int i = 0; i < 4; ++i)
            tile[ty + i * 8][tx] = w1[(size_t)(kb + ty + i * 8) * NDIM + nb + tx];
        __syncthreads();
#pragma unroll
        for (int i = 0; i < 4; ++i) {
            int row = ty + i * 8;
            float orig = tile[tx][row];
            float v = orig * 1024.0f;
            __half h = __float2half_rn(v);
            __half l = __float2half_rn(v - __half2float(h));
            size_t o = (size_t)(nb + row) * HDIM + kb + tx;
            g_wh[o] = h; g_wl[o] = l; g_w1tf[o] = orig;
        }
    } else {
        const int i = (b - 2048) * 256 + t;
        if (i < MTOK * NEXP) ew[i] = b2[i & 7];
        if (b == 2048) {
            if (t < NEXP) g_usage[t] = 0.f;
            if (t == 0) { g_count = 0; g_nflag = 0; }
        }
    }
}

// ---------- kernel 1: GEMM (ah*(bh+bl)) + GELU + GEMM2 (R9 2-stage, unchanged) ----
__global__ __launch_bounds__(256, 2)
void gemm_kernel(const float* __restrict__ x, const float* __restrict__ b1,
                 const float* __restrict__ w2, float* __restrict__ ew) {
    extern __shared__ char smem[];
    const uint32_t sb = smem_u32(smem);
    const int t = threadIdx.x, w = t >> 5, lane = t & 31;
    const int wm = w & 3, wn = w >> 2;
    const int n0 = blockIdx.x * BN, m0 = blockIdx.y * BM;

    float* w2s = (float*)(smem + OFF_W2);
    float* b1s = (float*)(smem + OFF_B1);
    for (int i = t; i < BN * NEXP; i += 256) w2s[i] = w2[(size_t)n0 * NEXP + i];
    for (int i = t; i < BN; i += 256)        b1s[i] = b1[n0 + i];

    const int rA = t >> 1;
    const float* xg = x + (size_t)(m0 + rA) * HDIM + (t & 1) * 16;
    const size_t gb0 = (size_t)(n0 + rA) * HDIM;

#define LOAD_B(stg, kt_)                                                     \
    {                                                                        \
        uint32_t _bs = sb + (stg) * STG + rA * 80;                           \
        size_t _kb = gb0 + (size_t)(kt_) * BK;                               \
        _Pragma("unroll")                                                    \
        for (int j = 0; j < 2; ++j) {                                        \
            int c16 = (t & 1) * 2 + j;                                       \
            cp16(_bs + ST_BH + c16 * 16, g_wh + _kb + c16 * 8);              \
            cp16(_bs + ST_BL + c16 * 16, g_wl + _kb + c16 * 8);              \
        }                                                                    \
    }

#define STS_A(stg, ra_)                                                      \
    {                                                                        \
        uint32_t hws[8];                                                     \
        _Pragma("unroll")                                                    \
        for (int wi = 0; wi < 4; ++wi) {                                     \
            const float* fp = (const float*)&(ra_)[wi];                      \
            __half2 p01 = __halves2half2(__float2half_rn(fp[0]),             \
                                         __float2half_rn(fp[1]));            \
            __half2 p23 = __halves2half2(__float2half_rn(fp[2]),             \
                                         __float2half_rn(fp[3]));            \
            hws[wi*2] = *(uint32_t*)&p01; hws[wi*2+1] = *(uint32_t*)&p23;    \
        }                                                                    \
        char* _p = smem + (stg) * STG + ST_AH + rA * 80 + (t & 1) * 32;      \
        *(uint4*)(_p)      = make_uint4(hws[0], hws[1], hws[2], hws[3]);     \
        *(uint4*)(_p + 16) = make_uint4(hws[4], hws[5], hws[6], hws[7]);     \
    }

    float4 ra[4];
#pragma unroll
    for (int i = 0; i < 4; ++i) ra[i] = *(const float4*)(xg + 4 * i);
    LOAD_B(0, 0); cp_commit();
    STS_A(0, ra);
#pragma unroll
    for (int i = 0; i < 4; ++i) ra[i] = *(const float4*)(xg + BK + 4 * i);

    float acc[2][8][4];
#pragma unroll
    for (int mi = 0; mi < 2; ++mi)
#pragma unroll
        for (int ni = 0; ni < 8; ++ni)
#pragma unroll
            for (int c = 0; c < 4; ++c) acc[mi][ni][c] = 0.f;

    const uint32_t aoff = ((lane & 7) + ((lane >> 3) & 1) * 8) * 80 + ((lane >> 4) & 1) * 16;
    const uint32_t* s32m = (const uint32_t*)smem;
    const int bword0 = (ST_BH + (wn * 64 + (lane >> 2)) * 80 + (lane & 3) * 4) >> 2;
    const int BLOFF = (ST_BL - ST_BH) >> 2;

    for (int kt = 0; kt < KT; ++kt) {
        cp_wait0();
        __syncthreads();
        if (kt + 1 < KT) { LOAD_B((kt + 1) & 1, kt + 1); cp_commit(); STS_A((kt + 1) & 1, ra); }
        if (kt + 2 < KT) {
#pragma unroll
            for (int i = 0; i < 4; ++i) ra[i] = *(const float4*)(xg + (kt + 2) * BK + 4 * i);
        }
        const uint32_t bs = sb + (kt & 1) * STG;
        const int sw = ((kt & 1) * STG) >> 2;
#pragma unroll
        for (int kk = 0; kk < 2; ++kk) {
            uint32_t ah[2][4];
#pragma unroll
            for (int mi = 0; mi < 2; ++mi)
                ldm4(ah[mi], bs + ST_AH + (wm * 32 + mi * 16) * 80 + kk * 32 + aoff);
#pragma unroll
            for (int ni = 0; ni < 8; ++ni) {
                int bo = sw + bword0 + (ni * 8 * 80 + kk * 32) / 4;
                uint32_t bh[2] = { s32m[bo], s32m[bo + 4] };
                uint32_t bl[2] = { s32m[bo + BLOFF], s32m[bo + BLOFF + 4] };
#pragma unroll
                for (int mi = 0; mi < 2; ++mi) {
                    mma(acc[mi][ni], ah[mi], bh);
                    mma(acc[mi][ni], ah[mi], bl);
                }
            }
        }
    }

    float part[4][NEXP];
#pragma unroll
    for (int p = 0; p < 4; ++p)
#pragma unroll
        for (int e = 0; e < NEXP; ++e) part[p][e] = 0.f;
    const float isc = 1.0f / 1024.0f;
#pragma unroll
    for (int mi = 0; mi < 2; ++mi)
#pragma unroll
        for (int h = 0; h < 2; ++h) {
            const int pi = mi * 2 + h;
#pragma unroll
            for (int ni = 0; ni < 8; ++ni) {
                int nl = wn * 64 + ni * 8 + (lane & 3) * 2;
                float v0 = acc[mi][ni][h * 2] * isc + b1s[nl];
                float v1 = acc[mi][ni][h * 2 + 1] * isc + b1s[nl + 1];
                float g0 = 0.5f * v0 * (1.0f + erff(v0 * 0.7071067811865475f));
                float g1 = 0.5f * v1 * (1.0f + erff(v1 * 0.7071067811865475f));
                const float* wr = w2s + nl * NEXP;
#pragma unroll
                for (int e = 0; e < NEXP; ++e)
                    part[pi][e] = fmaf(g0, wr[e], fmaf(g1, wr[NEXP + e], part[pi][e]));
            }
        }
#pragma unroll
    for (int p = 0; p < 4; ++p)
#pragma unroll
        for (int e = 0; e < NEXP; ++e) {
            float v = part[p][e];
            v += __shfl_xor_sync(0xffffffffu, v, 1);
            v += __shfl_xor_sync(0xffffffffu, v, 2);
            part[p][e] = v;
        }
    if ((lane & 3) == 0)
#pragma unroll
        for (int p = 0; p < 4; ++p) {
            int r = m0 + wm * 32 + (p >> 1) * 16 + (p & 1) * 8 + (lane >> 2);
#pragma unroll
            for (int e = 0; e < NEXP; ++e)
                atomicAdd(&ew[(size_t)r * NEXP + e], part[p][e]);
        }
}

// ---------- kernel 2: top-2 + masks + usage; flag near top2/top3 ties ----------
__global__ void topk_kernel(const float* __restrict__ ew, float* __restrict__ masks,
                            const float* __restrict__ b2, int M) {
    __shared__ float su[NEXP];
    __shared__ int sc;
    const int t = threadIdx.x;
    if (t < NEXP) su[t] = 0.f;
    if (t == 0)   sc = 0;
    __syncthreads();
    const int tok = blockIdx.x * blockDim.x + t;
    if (tok < M) {
        float v[NEXP];
        float4 a = *(const float4*)(ew + (size_t)tok * NEXP);
        float4 b = *(const float4*)(ew + (size_t)tok * NEXP + 4);
        v[0]=a.x; v[1]=a.y; v[2]=a.z; v[3]=a.w; v[4]=b.x; v[5]=b.y; v[6]=b.z; v[7]=b.w;
        int i1 = 0; float m1 = v[0];
#pragma unroll
        for (int e = 1; e < NEXP; ++e) if (v[e] > m1) { m1 = v[e]; i1 = e; }
        int i2 = -1; float m2 = -3.4e38f;
#pragma unroll
        for (int e = 0; e < NEXP; ++e) if (e != i1 && v[e] > m2) { m2 = v[e]; i2 = e; }
        float m3 = -3.4e38f;
#pragma unroll
        for (int e = 0; e < NEXP; ++e) if (e != i1 && e != i2 && v[e] > m3) m3 = v[e];
        bool flagged = false;
        if (m2 - m3 < GAP_TH) {
            int idx = atomicAdd(&g_nflag, 1);
            if (idx < MAXFLAG) {
                flagged = true;
                g_list[idx] = tok;
#pragma unroll
                for (int e = 0; e < NEXP; ++e) g_ewfix[idx * NEXP + e] = b2[e];
            }
        }
        if (!flagged) {
            float ex = expf(m2 - m1);
            float p1 = 1.f / (1.f + ex), p2 = ex / (1.f + ex);
            float o[NEXP];
#pragma unroll
            for (int e = 0; e < NEXP; ++e) o[e] = (e == i1) ? p1 : ((e == i2) ? p2 : 0.f);
            *(float4*)(masks + (size_t)tok * NEXP)     = make_float4(o[0], o[1], o[2], o[3]);
            *(float4*)(masks + (size_t)tok * NEXP + 4) = make_float4(o[4], o[5], o[6], o[7]);
            atomicAdd(&su[i1], p1);
            atomicAdd(&su[i2], p2);
            atomicAdd(&sc, (p1 > 0.f) + (p2 > 0.f));
        }
    }
    __syncthreads();
    if (t < NEXP) atomicAdd(&g_usage[t], su[t]);
    if (t == 0)   atomicAdd(&g_count, sc);
}

// ---------- kernel 3a: warp-per-row exact recompute (sync-free mainloop) ----------
// grid (8 n-blocks of 256, 64 token slots); warp computes 32 w-rows independently
__global__ __launch_bounds__(256)
void repairA_kernel(const float* __restrict__ x, const float* __restrict__ b1,
                    const float* __restrict__ w2) {
    __shared__ float xs[HDIM];
    const int t = threadIdx.x, w = t >> 5, lane = t & 31;
    const int nf = min(g_nflag, MAXFLAG);
    const int nb = blockIdx.x * 256;

    for (int it = blockIdx.y; it < nf; it += gridDim.y) {
        const int tok = g_list[it];
        __syncthreads();                       // xs reuse guard across iterations
        for (int i = t; i < HDIM; i += 256) xs[i] = x[(size_t)tok * HDIM + i];
        __syncthreads();

        float part = 0.f;                       // lanes 0-7 carry expert partials
#pragma unroll 4
        for (int r = 0; r < 32; ++r) {
            const int n = nb + w * 32 + r;
            const float* wp = g_w1tf + (size_t)n * HDIM + lane * 4;
            float s = 0.f;
#pragma unroll
            for (int kq = 0; kq < 8; ++kq) {
                float4 wv = *(const float4*)(wp + kq * 128);
                float4 xv = *(const float4*)&xs[kq * 128 + lane * 4];
                s = fmaf(xv.x, wv.x, fmaf(xv.y, wv.y,
                    fmaf(xv.z, wv.z, fmaf(xv.w, wv.w, s))));
            }
#pragma unroll
            for (int d = 16; d > 0; d >>= 1) s += __shfl_xor_sync(0xffffffffu, s, d);
            float v = s + b1[n];
            float g = 0.5f * v * (1.0f + erff(v * 0.7071067811865475f));
            if (lane < NEXP) part = fmaf(g, w2[n * NEXP + lane], part);
        }
        if (lane < NEXP) atomicAdd(&g_ewfix[it * NEXP + lane], part);
    }
}

// ---------- kernel 3b: flagged masks/usage + losses (single block) ----------
__global__ void repairB_kernel(float* __restrict__ masks, float* __restrict__ tail, int M) {
    __shared__ float su[NEXP];
    __shared__ int sc;
    const int t = threadIdx.x;
    if (t < NEXP) su[t] = 0.f;
    if (t == 0)   sc = 0;
    __syncthreads();
    const int nf = min(g_nflag, MAXFLAG);
    for (int it = t; it < nf; it += 256) {
        const int tok = g_list[it];
        float v[NEXP];
#pragma unroll
        for (int e = 0; e < NEXP; ++e) v[e] = g_ewfix[it * NEXP + e];
        int i1 = 0; float m1 = v[0];
#pragma unroll
        for (int e = 1; e < NEXP; ++e) if (v[e] > m1) { m1 = v[e]; i1 = e; }
        int i2 = -1; float m2 = -3.4e38f;
#pragma unroll
        for (int e = 0; e < NEXP; ++e) if (e != i1 && v[e] > m2) { m2 = v[e]; i2 = e; }
        float ex = expf(m2 - m1);
        float p1 = 1.f / (1.f + ex), p2 = ex / (1.f + ex);
        float o[NEXP];
#pragma unroll
        for (int e = 0; e < NEXP; ++e) o[e] = (e == i1) ? p1 : ((e == i2) ? p2 : 0.f);
        *(float4*)(masks + (size_t)tok * NEXP)     = make_float4(o[0], o[1], o[2], o[3]);
        *(float4*)(masks + (size_t)tok * NEXP + 4) = make_float4(o[4], o[5], o[6], o[7]);
        atomicAdd(&su[i1], p1);
        atomicAdd(&su[i2], p2);
        atomicAdd(&sc, (p1 > 0.f) + (p2 > 0.f));
    }
    __syncthreads();
    if (t == 0) {
        float u[NEXP], s = 0.f;
#pragma unroll
        for (int e = 0; e < NEXP; ++e) { u[e] = g_usage[e] + su[e]; s += u[e]; }
        float lb = 0.f;
#pragma unroll
        for (int e = 0; e < NEXP; ++e) {
            float un = u[e] / s;
            tail[1 + e] = un;
            float d = un - 0.125f;
            lb += d * d;
        }
        lb *= (1.f / 8.f);
        tail[0] = lb + 0.1f * (((float)(g_count + sc) / (float)M) * 0.5f);
    }
}

// ---------- launch ----------
extern "C" void kernel_launch(void* const* d_in, const int* in_sizes, int n_in,
                              void* d_out, int out_size) {
    const float* x  = (const float*)d_in[0];
    const float* w1 = (const float*)d_in[1];
    const float* b1 = (const float*)d_in[2];
    const float* w2 = (const float*)d_in[3];
    const float* b2 = (const float*)d_in[4];
    float* out   = (float*)d_out;
    const int M  = in_sizes[0] / HDIM;
    float* ew    = out;
    float* masks = out + (size_t)M * NEXP;
    float* tail  = out + (size_t)2 * M * NEXP;

    cudaFuncSetAttribute(gemm_kernel, cudaFuncAttributeMaxDynamicSharedMemorySize, SMEM_DYN);

    pre_kernel<<<2048 + (M * NEXP + 255) / 256, 256>>>(w1, ew, b2);
    gemm_kernel<<<dim3(NDIM / BN, M / BM), 256, SMEM_DYN>>>(x, b1, w2, ew);
    topk_kernel<<<(M + 255) / 256, 256>>>(ew, masks, b2, M);
    repairA_kernel<<<dim3(NDIM / 256, 64), 256>>>(x, b1, w2);
    repairB_kernel<<<1, 256>>>(masks, tail, M);
}

// round 16
// speedup vs baseline: 1.0486x; 1.0478x over previous
#include <cuda_runtime.h>
#include <cuda_fp16.h>
#include <math.h>
#include <stdint.h>

#define HDIM 1024
#define NDIM 2048
#define NEXP 8
#define MTOK 16384
#define BM 128
#define BN 128
#define BK 32
#define KT (HDIM / BK)
#define GAP_TH 5e-4f
#define MAXFLAG 1024

#define ST_AH 0
#define ST_BH 10240
#define ST_BL 20480
#define STG   30720
#define OFF_W2 (2 * STG)
#define OFF_B1 (OFF_W2 + BN * NEXP * 4)
#define SMEM_DYN (OFF_B1 + BN * 4)

__device__ __half g_wh[NDIM * HDIM];
__device__ __half g_wl[NDIM * HDIM];
__device__ float  g_w1tf[NDIM * HDIM];
__device__ float  g_vtmp[MAXFLAG * NDIM];     // partial v for flagged tokens (8 MB)
__device__ float  g_ewfix[MAXFLAG * NEXP];
__device__ float  g_usage[NEXP];
__device__ int    g_count, g_nflag;
__device__ int    g_list[MAXFLAG];

__device__ __forceinline__ uint32_t smem_u32(const void* p) {
    uint32_t a;
    asm("{ .reg .u64 t; cvta.to.shared.u64 t, %1; cvt.u32.u64 %0, t; }" : "=r"(a) : "l"(p));
    return a;
}
__device__ __forceinline__ void cp16(uint32_t s, const void* g) {
    asm volatile("cp.async.cg.shared.global [%0], [%1], 16;" :: "r"(s), "l"(g));
}
__device__ __forceinline__ void cp_commit() { asm volatile("cp.async.commit_group;" ::: "memory"); }
__device__ __forceinline__ void cp_wait0()  { asm volatile("cp.async.wait_group 0;" ::: "memory"); }
__device__ __forceinline__ void ldm4(uint32_t* r, uint32_t a) {
    asm volatile("ldmatrix.sync.aligned.m8n8.x4.shared.b16 {%0,%1,%2,%3}, [%4];"
                 : "=r"(r[0]), "=r"(r[1]), "=r"(r[2]), "=r"(r[3]) : "r"(a));
}
__device__ __forceinline__ void mma(float* c, const uint32_t* a, const uint32_t* b) {
    asm volatile("mma.sync.aligned.m16n8k16.row.col.f32.f16.f16.f32 "
                 "{%0,%1,%2,%3}, {%4,%5,%6,%7}, {%8,%9}, {%0,%1,%2,%3};"
                 : "+f"(c[0]), "+f"(c[1]), "+f"(c[2]), "+f"(c[3])
                 : "r"(a[0]), "r"(a[1]), "r"(a[2]), "r"(a[3]), "r"(b[0]), "r"(b[1]));
}

// ---------- kernel 0: w1^T split + ew init + vtmp zero ----------
__global__ void pre_kernel(const float* __restrict__ w1, float* __restrict__ ew,
                           const float* __restrict__ b2, int initB) {
    __shared__ float tile[32][33];
    const int b = blockIdx.x, t = threadIdx.x;
    if (b < 2048) {
        const int nb = (b & 63) * 32, kb = (b >> 6) * 32;
        const int tx = t & 31, ty = t >> 5;
#pragma unroll
        for (int i = 0; i < 4; ++i)
            tile[ty + i * 8][tx] = w1[(size_t)(kb + ty + i * 8) * NDIM + nb + tx];
        __syncthreads();
#pragma unroll
        for (int i = 0; i < 4; ++i) {
            int row = ty + i * 8;
            float orig = tile[tx][row];
            float v = orig * 1024.0f;
            __half h = __float2half_rn(v);
            __half l = __float2half_rn(v - __half2float(h));
            size_t o = (size_t)(nb + row) * HDIM + kb + tx;
            g_wh[o] = h; g_wl[o] = l; g_w1tf[o] = orig;
        }
    } else if (b < 2048 + initB) {
        const int i = (b - 2048) * 256 + t;
        if (i < MTOK * NEXP) ew[i] = b2[i & 7];
        if (b == 2048) {
            if (t < NEXP) g_usage[t] = 0.f;
            if (t == 0) { g_count = 0; g_nflag = 0; }
        }
    } else {
        const int i = (b - 2048 - initB) * 256 + t;   // float4 index
        ((float4*)g_vtmp)[i] = make_float4(0.f, 0.f, 0.f, 0.f);
    }
}

// ---------- kernel 1: GEMM (ah*(bh+bl)) + GELU + GEMM2 (R9 2-stage, unchanged) ----
__global__ __launch_bounds__(256, 2)
void gemm_kernel(const float* __restrict__ x, const float* __restrict__ b1,
                 const float* __restrict__ w2, float* __restrict__ ew) {
    extern __shared__ char smem[];
    const uint32_t sb = smem_u32(smem);
    const int t = threadIdx.x, w = t >> 5, lane = t & 31;
    const int wm = w & 3, wn = w >> 2;
    const int n0 = blockIdx.x * BN, m0 = blockIdx.y * BM;

    float* w2s = (float*)(smem + OFF_W2);
    float* b1s = (float*)(smem + OFF_B1);
    for (int i = t; i < BN * NEXP; i += 256) w2s[i] = w2[(size_t)n0 * NEXP + i];
    for (int i = t; i < BN; i += 256)        b1s[i] = b1[n0 + i];

    const int rA = t >> 1;
    const float* xg = x + (size_t)(m0 + rA) * HDIM + (t & 1) * 16;
    const size_t gb0 = (size_t)(n0 + rA) * HDIM;

#define LOAD_B(stg, kt_)                                                     \
    {                                                                        \
        uint32_t _bs = sb + (stg) * STG + rA * 80;                           \
        size_t _kb = gb0 + (size_t)(kt_) * BK;                               \
        _Pragma("unroll")                                                    \
        for (int j = 0; j < 2; ++j) {                                        \
            int c16 = (t & 1) * 2 + j;                                       \
            cp16(_bs + ST_BH + c16 * 16, g_wh + _kb + c16 * 8);              \
            cp16(_bs + ST_BL + c16 * 16, g_wl + _kb + c16 * 8);              \
        }                                                                    \
    }

#define STS_A(stg, ra_)                                                      \
    {                                                                        \
        uint32_t hws[8];                                                     \
        _Pragma("unroll")                                                    \
        for (int wi = 0; wi < 4; ++wi) {                                     \
            const float* fp = (const float*)&(ra_)[wi];                      \
            __half2 p01 = __halves2half2(__float2half_rn(fp[0]),             \
                                         __float2half_rn(fp[1]));            \
            __half2 p23 = __halves2half2(__float2half_rn(fp[2]),             \
                                         __float2half_rn(fp[3]));            \
            hws[wi*2] = *(uint32_t*)&p01; hws[wi*2+1] = *(uint32_t*)&p23;    \
        }                                                                    \
        char* _p = smem + (stg) * STG + ST_AH + rA * 80 + (t & 1) * 32;      \
        *(uint4*)(_p)      = make_uint4(hws[0], hws[1], hws[2], hws[3]);     \
        *(uint4*)(_p + 16) = make_uint4(hws[4], hws[5], hws[6], hws[7]);     \
    }

    float4 ra[4];
#pragma unroll
    for (int i = 0; i < 4; ++i) ra[i] = *(const float4*)(xg + 4 * i);
    LOAD_B(0, 0); cp_commit();
    STS_A(0, ra);
#pragma unroll
    for (int i = 0; i < 4; ++i) ra[i] = *(const float4*)(xg + BK + 4 * i);

    float acc[2][8][4];
#pragma unroll
    for (int mi = 0; mi < 2; ++mi)
#pragma unroll
        for (int ni = 0; ni < 8; ++ni)
#pragma unroll
            for (int c = 0; c < 4; ++c) acc[mi][ni][c] = 0.f;

    const uint32_t aoff = ((lane & 7) + ((lane >> 3) & 1) * 8) * 80 + ((lane >> 4) & 1) * 16;
    const uint32_t* s32m = (const uint32_t*)smem;
    const int bword0 = (ST_BH + (wn * 64 + (lane >> 2)) * 80 + (lane & 3) * 4) >> 2;
    const int BLOFF = (ST_BL - ST_BH) >> 2;

    for (int kt = 0; kt < KT; ++kt) {
        cp_wait0();
        __syncthreads();
        if (kt + 1 < KT) { LOAD_B((kt + 1) & 1, kt + 1); cp_commit(); STS_A((kt + 1) & 1, ra); }
        if (kt + 2 < KT) {
#pragma unroll
            for (int i = 0; i < 4; ++i) ra[i] = *(const float4*)(xg + (kt + 2) * BK + 4 * i);
        }
        const uint32_t bs = sb + (kt & 1) * STG;
        const int sw = ((kt & 1) * STG) >> 2;
#pragma unroll
        for (int kk = 0; kk < 2; ++kk) {
            uint32_t ah[2][4];
#pragma unroll
            for (int mi = 0; mi < 2; ++mi)
                ldm4(ah[mi], bs + ST_AH + (wm * 32 + mi * 16) * 80 + kk * 32 + aoff);
#pragma unroll
            for (int ni = 0; ni < 8; ++ni) {
                int bo = sw + bword0 + (ni * 8 * 80 + kk * 32) / 4;
                uint32_t bh[2] = { s32m[bo], s32m[bo + 4] };
                uint32_t bl[2] = { s32m[bo + BLOFF], s32m[bo + BLOFF + 4] };
#pragma unroll
                for (int mi = 0; mi < 2; ++mi) {
                    mma(acc[mi][ni], ah[mi], bh);
                    mma(acc[mi][ni], ah[mi], bl);
                }
            }
        }
    }

    float part[4][NEXP];
#pragma unroll
    for (int p = 0; p < 4; ++p)
#pragma unroll
        for (int e = 0; e < NEXP; ++e) part[p][e] = 0.f;
    const float isc = 1.0f / 1024.0f;
#pragma unroll
    for (int mi = 0; mi < 2; ++mi)
#pragma unroll
        for (int h = 0; h < 2; ++h) {
            const int pi = mi * 2 + h;
#pragma unroll
            for (int ni = 0; ni < 8; ++ni) {
                int nl = wn * 64 + ni * 8 + (lane & 3) * 2;
                float v0 = acc[mi][ni][h * 2] * isc + b1s[nl];
                float v1 = acc[mi][ni][h * 2 + 1] * isc + b1s[nl + 1];
                float g0 = 0.5f * v0 * (1.0f + erff(v0 * 0.7071067811865475f));
                float g1 = 0.5f * v1 * (1.0f + erff(v1 * 0.7071067811865475f));
                const float* wr = w2s + nl * NEXP;
#pragma unroll
                for (int e = 0; e < NEXP; ++e)
                    part[pi][e] = fmaf(g0, wr[e], fmaf(g1, wr[NEXP + e], part[pi][e]));
            }
        }
#pragma unroll
    for (int p = 0; p < 4; ++p)
#pragma unroll
        for (int e = 0; e < NEXP; ++e) {
            float v = part[p][e];
            v += __shfl_xor_sync(0xffffffffu, v, 1);
            v += __shfl_xor_sync(0xffffffffu, v, 2);
            part[p][e] = v;
        }
    if ((lane & 3) == 0)
#pragma unroll
        for (int p = 0; p < 4; ++p) {
            int r = m0 + wm * 32 + (p >> 1) * 16 + (p & 1) * 8 + (lane >> 2);
#pragma unroll
            for (int e = 0; e < NEXP; ++e)
                atomicAdd(&ew[(size_t)r * NEXP + e], part[p][e]);
        }
}

// ---------- kernel 2: top-2 + masks + usage; flag near top2/top3 ties ----------
__global__ void topk_kernel(const float* __restrict__ ew, float* __restrict__ masks,
                            const float* __restrict__ b2, int M) {
    __shared__ float su[NEXP];
    __shared__ int sc;
    const int t = threadIdx.x;
    if (t < NEXP) su[t] = 0.f;
    if (t == 0)   sc = 0;
    __syncthreads();
    const int tok = blockIdx.x * blockDim.x + t;
    if (tok < M) {
        float v[NEXP];
        float4 a = *(const float4*)(ew + (size_t)tok * NEXP);
        float4 b = *(const float4*)(ew + (size_t)tok * NEXP + 4);
        v[0]=a.x; v[1]=a.y; v[2]=a.z; v[3]=a.w; v[4]=b.x; v[5]=b.y; v[6]=b.z; v[7]=b.w;
        int i1 = 0; float m1 = v[0];
#pragma unroll
        for (int e = 1; e < NEXP; ++e) if (v[e] > m1) { m1 = v[e]; i1 = e; }
        int i2 = -1; float m2 = -3.4e38f;
#pragma unroll
        for (int e = 0; e < NEXP; ++e) if (e != i1 && v[e] > m2) { m2 = v[e]; i2 = e; }
        float m3 = -3.4e38f;
#pragma unroll
        for (int e = 0; e < NEXP; ++e) if (e != i1 && e != i2 && v[e] > m3) m3 = v[e];
        bool flagged = false;
        if (m2 - m3 < GAP_TH) {
            int idx = atomicAdd(&g_nflag, 1);
            if (idx < MAXFLAG) {
                flagged = true;
                g_list[idx] = tok;
#pragma unroll
                for (int e = 0; e < NEXP; ++e) g_ewfix[idx * NEXP + e] = b2[e];
            }
        }
        if (!flagged) {
            float ex = expf(m2 - m1);
            float p1 = 1.f / (1.f + ex), p2 = ex / (1.f + ex);
            float o[NEXP];
#pragma unroll
            for (int e = 0; e < NEXP; ++e) o[e] = (e == i1) ? p1 : ((e == i2) ? p2 : 0.f);
            *(float4*)(masks + (size_t)tok * NEXP)     = make_float4(o[0], o[1], o[2], o[3]);
            *(float4*)(masks + (size_t)tok * NEXP + 4) = make_float4(o[4], o[5], o[6], o[7]);
            atomicAdd(&su[i1], p1);
            atomicAdd(&su[i2], p2);
            atomicAdd(&sc, (p1 > 0.f) + (p2 > 0.f));
        }
    }
    __syncthreads();
    if (t < NEXP) atomicAdd(&g_usage[t], su[t]);
    if (t == 0)   atomicAdd(&g_count, sc);
}

// ---------- kernel 3a: repair phase A — pure partial GEMM into g_vtmp ----------
// grid (16 n-blocks, 4 k-blocks, 4 tok stripes); tile 16 tok x 128 n x 256 k
__global__ __launch_bounds__(256)
void repairA_kernel(const float* __restrict__ x) {
    __shared__ float xs[16][68];
    __shared__ float ws[128][68];
    const int t = threadIdx.x;
    const int nb = blockIdx.x * 128;
    const int k0 = blockIdx.y * 256;
    const int nfc = min(g_nflag, MAXFLAG);
    const int tg = t & 7, ng = t >> 3;     // 2 toks, 4 n per thread
    const int xrow = t >> 4, xcol = (t & 15) * 4;

    for (int tokbase = blockIdx.z * 16; tokbase < nfc; tokbase += 16 * gridDim.z) {
        float acc[2][4] = {{0.f, 0.f, 0.f, 0.f}, {0.f, 0.f, 0.f, 0.f}};
        const int ti = tokbase + xrow;
        const float* xrp = (ti < nfc) ? (x + (size_t)g_list[ti] * HDIM + k0) : 0;

        for (int kc = 0; kc < 4; ++kc) {
            __syncthreads();
            {   // xs: 16 tok x 64 k
                float4 v = make_float4(0.f, 0.f, 0.f, 0.f);
                if (xrp) v = *(const float4*)(xrp + kc * 64 + xcol);
                *(float4*)&xs[xrow][xcol] = v;
            }
#pragma unroll
            for (int i = 0; i < 8; ++i) {   // ws: 128 n x 64 k coalesced
                int idx = i * 256 + t;
                int row = idx >> 4, col = (idx & 15) * 4;
                *(float4*)&ws[row][col] =
                    *(const float4*)(g_w1tf + (size_t)(nb + row) * HDIM + k0 + kc * 64 + col);
            }
            __syncthreads();
#pragma unroll 4
            for (int kq = 0; kq < 16; ++kq) {
                float4 x0 = *(float4*)&xs[tg * 2][kq * 4];
                float4 x1 = *(float4*)&xs[tg * 2 + 1][kq * 4];
#pragma unroll
                for (int j = 0; j < 4; ++j) {
                    float4 wv = *(float4*)&ws[ng * 4 + j][kq * 4];
                    acc[0][j] = fmaf(x0.x, wv.x, fmaf(x0.y, wv.y,
                                fmaf(x0.z, wv.z, fmaf(x0.w, wv.w, acc[0][j]))));
                    acc[1][j] = fmaf(x1.x, wv.x, fmaf(x1.y, wv.y,
                                fmaf(x1.z, wv.z, fmaf(x1.w, wv.w, acc[1][j]))));
                }
            }
        }
#pragma unroll
        for (int i = 0; i < 2; ++i) {
            int it = tokbase + tg * 2 + i;
            if (it < nfc) {
#pragma unroll
                for (int j = 0; j < 4; ++j)
                    atomicAdd(&g_vtmp[(size_t)it * NDIM + nb + ng * 4 + j], acc[i][j]);
            }
        }
        __syncthreads();
    }
}

// ---------- kernel 3g: repair phase G — b1 + GELU + w2 contraction ----------
__global__ void repairG_kernel(const float* __restrict__ b1, const float* __restrict__ w2) {
    __shared__ float sew[NEXP];
    const int t = threadIdx.x, lane = t & 31;
    const int nfc = min(g_nflag, MAXFLAG);
    for (int it = blockIdx.x; it < nfc; it += gridDim.x) {
        if (t < NEXP) sew[t] = 0.f;
        __syncthreads();
        float part[NEXP];
#pragma unroll
        for (int e = 0; e < NEXP; ++e) part[e] = 0.f;
        for (int n = t; n < NDIM; n += 256) {
            float v = g_vtmp[(size_t)it * NDIM + n] + b1[n];
            float g = 0.5f * v * (1.0f + erff(v * 0.7071067811865475f));
#pragma unroll
            for (int e = 0; e < NEXP; ++e)
                part[e] = fmaf(g, w2[n * NEXP + e], part[e]);
        }
#pragma unroll
        for (int e = 0; e < NEXP; ++e) {
            float v = part[e];
#pragma unroll
            for (int d = 16; d > 0; d >>= 1) v += __shfl_xor_sync(0xffffffffu, v, d);
            if (lane == 0) atomicAdd(&sew[e], v);
        }
        __syncthreads();
        if (t < NEXP) atomicAdd(&g_ewfix[it * NEXP + t], sew[t]);
        __syncthreads();
    }
}

// ---------- kernel 3b: flagged masks/usage + losses (single block) ----------
__global__ void repairB_kernel(float* __restrict__ masks, float* __restrict__ tail, int M) {
    __shared__ float su[NEXP];
    __shared__ int sc;
    const int t = threadIdx.x;
    if (t < NEXP) su[t] = 0.f;
    if (t == 0)   sc = 0;
    __syncthreads();
    const int nf = min(g_nflag, MAXFLAG);
    for (int it = t; it < nf; it += 256) {
        const int tok = g_list[it];
        float v[NEXP];
#pragma unroll
        for (int e = 0; e < NEXP; ++e) v[e] = g_ewfix[it * NEXP + e];
        int i1 = 0; float m1 = v[0];
#pragma unroll
        for (int e = 1; e < NEXP; ++e) if (v[e] > m1) { m1 = v[e]; i1 = e; }
        int i2 = -1; float m2 = -3.4e38f;
#pragma unroll
        for (int e = 0; e < NEXP; ++e) if (e != i1 && v[e] > m2) { m2 = v[e]; i2 = e; }
        float ex = expf(m2 - m1);
        float p1 = 1.f / (1.f + ex), p2 = ex / (1.f + ex);
        float o[NEXP];
#pragma unroll
        for (int e = 0; e < NEXP; ++e) o[e] = (e == i1) ? p1 : ((e == i2) ? p2 : 0.f);
        *(float4*)(masks + (size_t)tok * NEXP)     = make_float4(o[0], o[1], o[2], o[3]);
        *(float4*)(masks + (size_t)tok * NEXP + 4) = make_float4(o[4], o[5], o[6], o[7]);
        atomicAdd(&su[i1], p1);
        atomicAdd(&su[i2], p2);
        atomicAdd(&sc, (p1 > 0.f) + (p2 > 0.f));
    }
    __syncthreads();
    if (t == 0) {
        float u[NEXP], s = 0.f;
#pragma unroll
        for (int e = 0; e < NEXP; ++e) { u[e] = g_usage[e] + su[e]; s += u[e]; }
        float lb = 0.f;
#pragma unroll
        for (int e = 0; e < NEXP; ++e) {
            float un = u[e] / s;
            tail[1 + e] = un;
            float d = un - 0.125f;
            lb += d * d;
        }
        lb *= (1.f / 8.f);
        tail[0] = lb + 0.1f * (((float)(g_count + sc) / (float)M) * 0.5f);
    }
}

// ---------- launch ----------
extern "C" void kernel_launch(void* const* d_in, const int* in_sizes, int n_in,
                              void* d_out, int out_size) {
    const float* x  = (const float*)d_in[0];
    const float* w1 = (const float*)d_in[1];
    const float* b1 = (const float*)d_in[2];
    const float* w2 = (const float*)d_in[3];
    const float* b2 = (const float*)d_in[4];
    float* out   = (float*)d_out;
    const int M  = in_sizes[0] / HDIM;
    float* ew    = out;
    float* masks = out + (size_t)M * NEXP;
    float* tail  = out + (size_t)2 * M * NEXP;

    cudaFuncSetAttribute(gemm_kernel, cudaFuncAttributeMaxDynamicSharedMemorySize, SMEM_DYN);

    const int initB = (M * NEXP + 255) / 256;
    const int vtmpB = (MAXFLAG * NDIM / 4 + 255) / 256;   // float4 zero blocks (2048)
    pre_kernel<<<2048 + initB + vtmpB, 256>>>(w1, ew, b2, initB);
    gemm_kernel<<<dim3(NDIM / BN, M / BM), 256, SMEM_DYN>>>(x, b1, w2, ew);
    topk_kernel<<<(M + 255) / 256, 256>>>(ew, masks, b2, M);
    repairA_kernel<<<dim3(16, 4, 4), 256>>>(x);
    repairG_kernel<<<64, 256>>>(b1, w2);
    repairB_kernel<<<1, 256>>>(masks, tail, M);
}

// round 17
// speedup vs baseline: 1.0533x; 1.0045x over previous
#include <cuda_runtime.h>
#include <cuda_fp16.h>
#include <math.h>
#include <stdint.h>

#define HDIM 1024
#define NDIM 2048
#define NEXP 8
#define MTOK 16384
#define BM 128
#define BN 128
#define BK 32
#define KT (HDIM / BK)
#define GAP_TH 5e-4f
#define MAXFLAG 1024

#define ST_AH 0
#define ST_BH 10240
#define ST_BL 20480
#define STG   30720
#define OFF_W2 (2 * STG)
#define OFF_B1 (OFF_W2 + BN * NEXP * 4)
#define SMEM_DYN (OFF_B1 + BN * 4)

__device__ __half g_wh[NDIM * HDIM];
__device__ __half g_wl[NDIM * HDIM];
__device__ float  g_w1tf[NDIM * HDIM];
__device__ float  g_vtmp[MAXFLAG * NDIM];     // partial v for flagged tokens (8 MB)
__device__ float  g_ewfix[MAXFLAG * NEXP];
__device__ float  g_usage[NEXP];
__device__ int    g_count, g_nflag, g_done;
__device__ int    g_list[MAXFLAG];

__device__ __forceinline__ uint32_t smem_u32(const void* p) {
    uint32_t a;
    asm("{ .reg .u64 t; cvta.to.shared.u64 t, %1; cvt.u32.u64 %0, t; }" : "=r"(a) : "l"(p));
    return a;
}
__device__ __forceinline__ void cp16(uint32_t s, const void* g) {
    asm volatile("cp.async.cg.shared.global [%0], [%1], 16;" :: "r"(s), "l"(g));
}
__device__ __forceinline__ void cp_commit() { asm volatile("cp.async.commit_group;" ::: "memory"); }
__device__ __forceinline__ void cp_wait0()  { asm volatile("cp.async.wait_group 0;" ::: "memory"); }
__device__ __forceinline__ void ldm4(uint32_t* r, uint32_t a) {
    asm volatile("ldmatrix.sync.aligned.m8n8.x4.shared.b16 {%0,%1,%2,%3}, [%4];"
                 : "=r"(r[0]), "=r"(r[1]), "=r"(r[2]), "=r"(r[3]) : "r"(a));
}
__device__ __forceinline__ void mma(float* c, const uint32_t* a, const uint32_t* b) {
    asm volatile("mma.sync.aligned.m16n8k16.row.col.f32.f16.f16.f32 "
                 "{%0,%1,%2,%3}, {%4,%5,%6,%7}, {%8,%9}, {%0,%1,%2,%3};"
                 : "+f"(c[0]), "+f"(c[1]), "+f"(c[2]), "+f"(c[3])
                 : "r"(a[0]), "r"(a[1]), "r"(a[2]), "r"(a[3]), "r"(b[0]), "r"(b[1]));
}

// ---------- kernel 0: w1^T split + ew init + vtmp zero ----------
__global__ void pre_kernel(const float* __restrict__ w1, float* __restrict__ ew,
                           const float* __restrict__ b2, int initB) {
    __shared__ float tile[32][33];
    const int b = blockIdx.x, t = threadIdx.x;
    if (b < 2048) {
        const int nb = (b & 63) * 32, kb = (b >> 6) * 32;
        const int tx = t & 31, ty = t >> 5;
#pragma unroll
        for (int i = 0; i < 4; ++i)
            tile[ty + i * 8][tx] = w1[(size_t)(kb + ty + i * 8) * NDIM + nb + tx];
        __syncthreads();
#pragma unroll
        for (int i = 0; i < 4; ++i) {
            int row = ty + i * 8;
            float orig = tile[tx][row];
            float v = orig * 1024.0f;
            __half h = __float2half_rn(v);
            __half l = __float2half_rn(v - __half2float(h));
            size_t o = (size_t)(nb + row) * HDIM + kb + tx;
            g_wh[o] = h; g_wl[o] = l; g_w1tf[o] = orig;
        }
    } else if (b < 2048 + initB) {
        const int i = (b - 2048) * 256 + t;
        if (i < MTOK * NEXP) ew[i] = b2[i & 7];
        if (b == 2048) {
            if (t < NEXP) g_usage[t] = 0.f;
            if (t == 0) { g_count = 0; g_nflag = 0; g_done = 0; }
        }
    } else {
        const int i = (b - 2048 - initB) * 256 + t;   // float4 index
        ((float4*)g_vtmp)[i] = make_float4(0.f, 0.f, 0.f, 0.f);
    }
}

// ---------- kernel 1: GEMM (ah*(bh+bl)) + GELU + GEMM2 (R9 2-stage, FROZEN) ----
__global__ __launch_bounds__(256, 2)
void gemm_kernel(const float* __restrict__ x, const float* __restrict__ b1,
                 const float* __restrict__ w2, float* __restrict__ ew) {
    extern __shared__ char smem[];
    const uint32_t sb = smem_u32(smem);
    const int t = threadIdx.x, w = t >> 5, lane = t & 31;
    const int wm = w & 3, wn = w >> 2;
    const int n0 = blockIdx.x * BN, m0 = blockIdx.y * BM;

    float* w2s = (float*)(smem + OFF_W2);
    float* b1s = (float*)(smem + OFF_B1);
    for (int i = t; i < BN * NEXP; i += 256) w2s[i] = w2[(size_t)n0 * NEXP + i];
    for (int i = t; i < BN; i += 256)        b1s[i] = b1[n0 + i];

    const int rA = t >> 1;
    const float* xg = x + (size_t)(m0 + rA) * HDIM + (t & 1) * 16;
    const size_t gb0 = (size_t)(n0 + rA) * HDIM;

#define LOAD_B(stg, kt_)                                                     \
    {                                                                        \
        uint32_t _bs = sb + (stg) * STG + rA * 80;                           \
        size_t _kb = gb0 + (size_t)(kt_) * BK;                               \
        _Pragma("unroll")                                                    \
        for (int j = 0; j < 2; ++j) {                                        \
            int c16 = (t & 1) * 2 + j;                                       \
            cp16(_bs + ST_BH + c16 * 16, g_wh + _kb + c16 * 8);              \
            cp16(_bs + ST_BL + c16 * 16, g_wl + _kb + c16 * 8);              \
        }                                                                    \
    }

#define STS_A(stg, ra_)                                                      \
    {                                                                        \
        uint32_t hws[8];                                                     \
        _Pragma("unroll")                                                    \
        for (int wi = 0; wi < 4; ++wi) {                                     \
            const float* fp = (const float*)&(ra_)[wi];                      \
            __half2 p01 = __halves2half2(__float2half_rn(fp[0]),             \
                                         __float2half_rn(fp[1]));            \
            __half2 p23 = __halves2half2(__float2half_rn(fp[2]),             \
                                         __float2half_rn(fp[3]));            \
            hws[wi*2] = *(uint32_t*)&p01; hws[wi*2+1] = *(uint32_t*)&p23;    \
        }                                                                    \
        char* _p = smem + (stg) * STG + ST_AH + rA * 80 + (t & 1) * 32;      \
        *(uint4*)(_p)      = make_uint4(hws[0], hws[1], hws[2], hws[3]);     \
        *(uint4*)(_p + 16) = make_uint4(hws[4], hws[5], hws[6], hws[7]);     \
    }

    float4 ra[4];
#pragma unroll
    for (int i = 0; i < 4; ++i) ra[i] = *(const float4*)(xg + 4 * i);
    LOAD_B(0, 0); cp_commit();
    STS_A(0, ra);
#pragma unroll
    for (int i = 0; i < 4; ++i) ra[i] = *(const float4*)(xg + BK + 4 * i);

    float acc[2][8][4];
#pragma unroll
    for (int mi = 0; mi < 2; ++mi)
#pragma unroll
        for (int ni = 0; ni < 8; ++ni)
#pragma unroll
            for (int c = 0; c < 4; ++c) acc[mi][ni][c] = 0.f;

    const uint32_t aoff = ((lane & 7) + ((lane >> 3) & 1) * 8) * 80 + ((lane >> 4) & 1) * 16;
    const uint32_t* s32m = (const uint32_t*)smem;
    const int bword0 = (ST_BH + (wn * 64 + (lane >> 2)) * 80 + (lane & 3) * 4) >> 2;
    const int BLOFF = (ST_BL - ST_BH) >> 2;

    for (int kt = 0; kt < KT; ++kt) {
        cp_wait0();
        __syncthreads();
        if (kt + 1 < KT) { LOAD_B((kt + 1) & 1, kt + 1); cp_commit(); STS_A((kt + 1) & 1, ra); }
        if (kt + 2 < KT) {
#pragma unroll
            for (int i = 0; i < 4; ++i) ra[i] = *(const float4*)(xg + (kt + 2) * BK + 4 * i);
        }
        const uint32_t bs = sb + (kt & 1) * STG;
        const int sw = ((kt & 1) * STG) >> 2;
#pragma unroll
        for (int kk = 0; kk < 2; ++kk) {
            uint32_t ah[2][4];
#pragma unroll
            for (int mi = 0; mi < 2; ++mi)
                ldm4(ah[mi], bs + ST_AH + (wm * 32 + mi * 16) * 80 + kk * 32 + aoff);
#pragma unroll
            for (int ni = 0; ni < 8; ++ni) {
                int bo = sw + bword0 + (ni * 8 * 80 + kk * 32) / 4;
                uint32_t bh[2] = { s32m[bo], s32m[bo + 4] };
                uint32_t bl[2] = { s32m[bo + BLOFF], s32m[bo + BLOFF + 4] };
#pragma unroll
                for (int mi = 0; mi < 2; ++mi) {
                    mma(acc[mi][ni], ah[mi], bh);
                    mma(acc[mi][ni], ah[mi], bl);
                }
            }
        }
    }

    float part[4][NEXP];
#pragma unroll
    for (int p = 0; p < 4; ++p)
#pragma unroll
        for (int e = 0; e < NEXP; ++e) part[p][e] = 0.f;
    const float isc = 1.0f / 1024.0f;
#pragma unroll
    for (int mi = 0; mi < 2; ++mi)
#pragma unroll
        for (int h = 0; h < 2; ++h) {
            const int pi = mi * 2 + h;
#pragma unroll
            for (int ni = 0; ni < 8; ++ni) {
                int nl = wn * 64 + ni * 8 + (lane & 3) * 2;
                float v0 = acc[mi][ni][h * 2] * isc + b1s[nl];
                float v1 = acc[mi][ni][h * 2 + 1] * isc + b1s[nl + 1];
                float g0 = 0.5f * v0 * (1.0f + erff(v0 * 0.7071067811865475f));
                float g1 = 0.5f * v1 * (1.0f + erff(v1 * 0.7071067811865475f));
                const float* wr = w2s + nl * NEXP;
#pragma unroll
                for (int e = 0; e < NEXP; ++e)
                    part[pi][e] = fmaf(g0, wr[e], fmaf(g1, wr[NEXP + e], part[pi][e]));
            }
        }
#pragma unroll
    for (int p = 0; p < 4; ++p)
#pragma unroll
        for (int e = 0; e < NEXP; ++e) {
            float v = part[p][e];
            v += __shfl_xor_sync(0xffffffffu, v, 1);
            v += __shfl_xor_sync(0xffffffffu, v, 2);
            part[p][e] = v;
        }
    if ((lane & 3) == 0)
#pragma unroll
        for (int p = 0; p < 4; ++p) {
            int r = m0 + wm * 32 + (p >> 1) * 16 + (p & 1) * 8 + (lane >> 2);
#pragma unroll
            for (int e = 0; e < NEXP; ++e)
                atomicAdd(&ew[(size_t)r * NEXP + e], part[p][e]);
        }
}

// ---------- kernel 2: top-2 + masks + usage; flag near top2/top3 ties ----------
__global__ void topk_kernel(const float* __restrict__ ew, float* __restrict__ masks,
                            const float* __restrict__ b2, int M) {
    __shared__ float su[NEXP];
    __shared__ int sc;
    const int t = threadIdx.x;
    if (t < NEXP) su[t] = 0.f;
    if (t == 0)   sc = 0;
    __syncthreads();
    const int tok = blockIdx.x * blockDim.x + t;
    if (tok < M) {
        float v[NEXP];
        float4 a = *(const float4*)(ew + (size_t)tok * NEXP);
        float4 b = *(const float4*)(ew + (size_t)tok * NEXP + 4);
        v[0]=a.x; v[1]=a.y; v[2]=a.z; v[3]=a.w; v[4]=b.x; v[5]=b.y; v[6]=b.z; v[7]=b.w;
        int i1 = 0; float m1 = v[0];
#pragma unroll
        for (int e = 1; e < NEXP; ++e) if (v[e] > m1) { m1 = v[e]; i1 = e; }
        int i2 = -1; float m2 = -3.4e38f;
#pragma unroll
        for (int e = 0; e < NEXP; ++e) if (e != i1 && v[e] > m2) { m2 = v[e]; i2 = e; }
        float m3 = -3.4e38f;
#pragma unroll
        for (int e = 0; e < NEXP; ++e) if (e != i1 && e != i2 && v[e] > m3) m3 = v[e];
        bool flagged = false;
        if (m2 - m3 < GAP_TH) {
            int idx = atomicAdd(&g_nflag, 1);
            if (idx < MAXFLAG) {
                flagged = true;
                g_list[idx] = tok;
#pragma unroll
                for (int e = 0; e < NEXP; ++e) g_ewfix[idx * NEXP + e] = b2[e];
            }
        }
        if (!flagged) {
            float ex = expf(m2 - m1);
            float p1 = 1.f / (1.f + ex), p2 = ex / (1.f + ex);
            float o[NEXP];
#pragma unroll
            for (int e = 0; e < NEXP; ++e) o[e] = (e == i1) ? p1 : ((e == i2) ? p2 : 0.f);
            *(float4*)(masks + (size_t)tok * NEXP)     = make_float4(o[0], o[1], o[2], o[3]);
            *(float4*)(masks + (size_t)tok * NEXP + 4) = make_float4(o[4], o[5], o[6], o[7]);
            atomicAdd(&su[i1], p1);
            atomicAdd(&su[i2], p2);
            atomicAdd(&sc, (p1 > 0.f) + (p2 > 0.f));
        }
    }
    __syncthreads();
    if (t < NEXP) atomicAdd(&g_usage[t], su[t]);
    if (t == 0)   atomicAdd(&g_count, sc);
}

// ---------- kernel 3a: repair phase A — partial GEMM into g_vtmp, prefetched ----
// grid (16 n-blocks, 4 k-blocks, 4 tok stripes); tile 16 tok x 128 n x 256 k
__global__ __launch_bounds__(256)
void repairA_kernel(const float* __restrict__ x) {
    __shared__ float xs[2][16][68];
    __shared__ float ws[2][128][68];
    const int t = threadIdx.x;
    const int nb = blockIdx.x * 128;
    const int k0 = blockIdx.y * 256;
    const int nfc = min(g_nflag, MAXFLAG);
    if ((int)blockIdx.z * 16 >= nfc) return;
    const int tg = t & 7, ng = t >> 3;     // 2 toks, 4 n per thread
    const int xrow = t >> 4, xcol = (t & 15) * 4;

    for (int tokbase = blockIdx.z * 16; tokbase < nfc; tokbase += 16 * gridDim.z) {
        float acc[2][4] = {{0.f, 0.f, 0.f, 0.f}, {0.f, 0.f, 0.f, 0.f}};
        const int ti = tokbase + xrow;
        const float* xrp = (ti < nfc) ? (x + (size_t)g_list[ti] * HDIM + k0) : 0;

        // prefetch kc=0
        float4 xr = xrp ? *(const float4*)(xrp + xcol) : make_float4(0.f, 0.f, 0.f, 0.f);
        float4 wr[8];
#pragma unroll
        for (int i = 0; i < 8; ++i) {
            int idx = i * 256 + t;
            wr[i] = *(const float4*)(g_w1tf + (size_t)(nb + (idx >> 4)) * HDIM
                                     + k0 + (idx & 15) * 4);
        }

        for (int kc = 0; kc < 4; ++kc) {
            const int buf = kc & 1;
            *(float4*)&xs[buf][xrow][xcol] = xr;
#pragma unroll
            for (int i = 0; i < 8; ++i) {
                int idx = i * 256 + t;
                *(float4*)&ws[buf][idx >> 4][(idx & 15) * 4] = wr[i];
            }
            __syncthreads();
            if (kc + 1 < 4) {   // prefetch next chunk; latency hidden under compute
                xr = xrp ? *(const float4*)(xrp + (kc + 1) * 64 + xcol)
                         : make_float4(0.f, 0.f, 0.f, 0.f);
#pragma unroll
                for (int i = 0; i < 8; ++i) {
                    int idx = i * 256 + t;
                    wr[i] = *(const float4*)(g_w1tf + (size_t)(nb + (idx >> 4)) * HDIM
                                             + k0 + (kc + 1) * 64 + (idx & 15) * 4);
                }
            }
#pragma unroll 4
            for (int kq = 0; kq < 16; ++kq) {
                float4 x0 = *(float4*)&xs[buf][tg * 2][kq * 4];
                float4 x1 = *(float4*)&xs[buf][tg * 2 + 1][kq * 4];
#pragma unroll
                for (int j = 0; j < 4; ++j) {
                    float4 wv = *(float4*)&ws[buf][ng * 4 + j][kq * 4];
                    acc[0][j] = fmaf(x0.x, wv.x, fmaf(x0.y, wv.y,
                                fmaf(x0.z, wv.z, fmaf(x0.w, wv.w, acc[0][j]))));
                    acc[1][j] = fmaf(x1.x, wv.x, fmaf(x1.y, wv.y,
                                fmaf(x1.z, wv.z, fmaf(x1.w, wv.w, acc[1][j]))));
                }
            }
        }
#pragma unroll
        for (int i = 0; i < 2; ++i) {
            int it = tokbase + tg * 2 + i;
            if (it < nfc) {
#pragma unroll
                for (int j = 0; j < 4; ++j)
                    atomicAdd(&g_vtmp[(size_t)it * NDIM + nb + ng * 4 + j], acc[i][j]);
            }
        }
        __syncthreads();
    }
}

// ---------- kernel 3b: repair finish — GELU+w2, masks/usage, last block: losses ----
__global__ void repairF_kernel(const float* __restrict__ b1, const float* __restrict__ w2,
                               float* __restrict__ masks, float* __restrict__ tail, int M) {
    __shared__ float sew[NEXP];
    __shared__ float su[NEXP];
    __shared__ int sc;
    const int t = threadIdx.x, lane = t & 31;
    if (t < NEXP) su[t] = 0.f;
    if (t == 0)   sc = 0;
    __syncthreads();
    const int nfc = min(g_nflag, MAXFLAG);
    for (int it = blockIdx.x; it < nfc; it += gridDim.x) {
        if (t < NEXP) sew[t] = g_ewfix[it * NEXP + t];   // seeded with b2
        __syncthreads();
        float part[NEXP];
#pragma unroll
        for (int e = 0; e < NEXP; ++e) part[e] = 0.f;
        for (int n = t; n < NDIM; n += 256) {
            float v = g_vtmp[(size_t)it * NDIM + n] + b1[n];
            float g = 0.5f * v * (1.0f + erff(v * 0.7071067811865475f));
#pragma unroll
            for (int e = 0; e < NEXP; ++e)
                part[e] = fmaf(g, w2[n * NEXP + e], part[e]);
        }
#pragma unroll
        for (int e = 0; e < NEXP; ++e) {
            float v = part[e];
#pragma unroll
            for (int d = 16; d > 0; d >>= 1) v += __shfl_xor_sync(0xffffffffu, v, d);
            if (lane == 0) atomicAdd(&sew[e], v);
        }
        __syncthreads();
        if (t == 0) {
            const int tok = g_list[it];
            float v[NEXP];
#pragma unroll
            for (int e = 0; e < NEXP; ++e) v[e] = sew[e];
            int i1 = 0; float m1 = v[0];
#pragma unroll
            for (int e = 1; e < NEXP; ++e) if (v[e] > m1) { m1 = v[e]; i1 = e; }
            int i2 = -1; float m2 = -3.4e38f;
#pragma unroll
            for (int e = 0; e < NEXP; ++e) if (e != i1 && v[e] > m2) { m2 = v[e]; i2 = e; }
            float ex = expf(m2 - m1);
            float p1 = 1.f / (1.f + ex), p2 = ex / (1.f + ex);
            float o[NEXP];
#pragma unroll
            for (int e = 0; e < NEXP; ++e) o[e] = (e == i1) ? p1 : ((e == i2) ? p2 : 0.f);
            *(float4*)(masks + (size_t)tok * NEXP)     = make_float4(o[0], o[1], o[2], o[3]);
            *(float4*)(masks + (size_t)tok * NEXP + 4) = make_float4(o[4], o[5], o[6], o[7]);
            atomicAdd(&su[i1], p1);
            atomicAdd(&su[i2], p2);
            atomicAdd(&sc, (p1 > 0.f) + (p2 > 0.f));
        }
        __syncthreads();
    }
    // fold block-local usage into globals, then last block computes losses
    if (t < NEXP) atomicAdd(&g_usage[t], su[t]);
    if (t == 0)   atomicAdd(&g_count, sc);
    __threadfence();
    __syncthreads();
    if (t == 0 && atomicAdd(&g_done, 1) == (int)gridDim.x - 1) {
        __threadfence();
        float u[NEXP], s = 0.f;
#pragma unroll
        for (int e = 0; e < NEXP; ++e) { u[e] = g_usage[e]; s += u[e]; }
        float lb = 0.f;
#pragma unroll
        for (int e = 0; e < NEXP; ++e) {
            float un = u[e] / s;
            tail[1 + e] = un;
            float d = un - 0.125f;
            lb += d * d;
        }
        lb *= (1.f / 8.f);
        tail[0] = lb + 0.1f * (((float)g_count / (float)M) * 0.5f);
    }
}

// ---------- launch ----------
extern "C" void kernel_launch(void* const* d_in, const int* in_sizes, int n_in,
                              void* d_out, int out_size) {
    const float* x  = (const float*)d_in[0];
    const float* w1 = (const float*)d_in[1];
    const float* b1 = (const float*)d_in[2];
    const float* w2 = (const float*)d_in[3];
    const float* b2 = (const float*)d_in[4];
    float* out   = (float*)d_out;
    const int M  = in_sizes[0] / HDIM;
    float* ew    = out;
    float* masks = out + (size_t)M * NEXP;
    float* tail  = out + (size_t)2 * M * NEXP;

    cudaFuncSetAttribute(gemm_kernel, cudaFuncAttributeMaxDynamicSharedMemorySize, SMEM_DYN);

    const int initB = (M * NEXP + 255) / 256;
    const int vtmpB = (MAXFLAG * NDIM / 4 + 255) / 256;
    pre_kernel<<<2048 + initB + vtmpB, 256>>>(w1, ew, b2, initB);
    gemm_kernel<<<dim3(NDIM / BN, M / BM), 256, SMEM_DYN>>>(x, b1, w2, ew);
    topk_kernel<<<(M + 255) / 256, 256>>>(ew, masks, b2, M);
    repairA_kernel<<<dim3(16, 4, 4), 256>>>(x);
    repairF_kernel<<<64, 256>>>(b1, w2, masks, tail, M);
}